// round 7
// baseline (speedup 1.0000x reference)
#include <cuda_runtime.h>
#include <math.h>
#include <stdint.h>

// Problem constants
#define T_STEPS  256
#define BATCH    64
#define VOCAB    32000
#define D_EMBED  512
#define D_HIDDEN 1024
#define G4       (4 * D_HIDDEN)          // 4096
#define NH       (BATCH * D_HIDDEN)      // 65536
#define NCTA     128

// Scratch
__device__ float    g_xgates[(size_t)T_STEPS * BATCH * G4];   // 256 MiB fp32
__device__ unsigned g_emb_tf32[(size_t)VOCAB * D_EMBED];      // tf32 bits
__device__ unsigned g_wih_tf32[(size_t)G4 * D_EMBED];
__device__ unsigned g_h_perm[2][NH];     // ping-pong h, fragment-major tf32
__device__ unsigned g_flags[NCTA];       // per-CTA step completion flags

// ---------------------------------------------------------------------------
// Helpers
// ---------------------------------------------------------------------------
__device__ __forceinline__ unsigned f2tf32(float f) {
    unsigned u;
    asm("cvt.rna.tf32.f32 %0, %1;" : "=r"(u) : "f"(f));
    return u;
}

__device__ __forceinline__ void cpa16(unsigned dst_s, const void* src) {
    asm volatile("cp.async.cg.shared.global [%0], [%1], 16;" :: "r"(dst_s), "l"(src));
}
__device__ __forceinline__ void cpa_commit() {
    asm volatile("cp.async.commit_group;");
}
__device__ __forceinline__ void cpa_wait1() {
    asm volatile("cp.async.wait_group 1;");
}
__device__ __forceinline__ void cpa_wait0() {
    asm volatile("cp.async.wait_group 0;");
}

__device__ __forceinline__ void mma_tf32(float c[4],
                                         unsigned a0, unsigned a1, unsigned a2, unsigned a3,
                                         unsigned b0, unsigned b1) {
    asm volatile(
        "mma.sync.aligned.m16n8k8.row.col.f32.tf32.tf32.f32 "
        "{%0,%1,%2,%3}, {%4,%5,%6,%7}, {%8,%9}, {%0,%1,%2,%3};"
        : "+f"(c[0]), "+f"(c[1]), "+f"(c[2]), "+f"(c[3])
        : "r"(a0), "r"(a1), "r"(a2), "r"(a3), "r"(b0), "r"(b1));
}

// Fast sigmoid/tanh via MUFU; abs err ~1e-6, safe vs 1e-3 threshold.
__device__ __forceinline__ float sigf(float x) {
    return __fdividef(1.0f, 1.0f + __expf(-x));
}
__device__ __forceinline__ float tanh_f(float x) {
    return 2.0f * __fdividef(1.0f, 1.0f + __expf(-2.0f * x)) - 1.0f;
}

// ---------------------------------------------------------------------------
// Init: reset inter-CTA flags (fresh every launch for graph replay)
// ---------------------------------------------------------------------------
__global__ void init_kernel() {
    if (threadIdx.x < NCTA) g_flags[threadIdx.x] = 0;
}

// ---------------------------------------------------------------------------
// fp32 -> tf32 (rna) bulk convert, vectorized x4
// ---------------------------------------------------------------------------
__global__ void cvt_tf32_kernel(const float4* __restrict__ src,
                                uint4* __restrict__ dst, int n4) {
    int i = blockIdx.x * blockDim.x + threadIdx.x;
    if (i < n4) {
        float4 v = src[i];
        uint4 o;
        o.x = f2tf32(v.x); o.y = f2tf32(v.y);
        o.z = f2tf32(v.z); o.w = f2tf32(v.w);
        dst[i] = o;
    }
}

// ---------------------------------------------------------------------------
// Embed gather + input GEMM (tf32 tensor cores)  [unchanged — passing]
// ---------------------------------------------------------------------------
#define EA_STRIDE 36
#define EA_BUF    (128 * EA_STRIDE)
#define E_B_OFF   (2 * EA_BUF)
#define E_TOK_OFF (4 * EA_BUF)
#define E_SMEM_WORDS (E_TOK_OFF + 128)
#define E_SMEM_BYTES (E_SMEM_WORDS * 4)

__global__ __launch_bounds__(256, 2)
void embed_gemm_tf32(const int* __restrict__ x_seq,
                     const float* __restrict__ b_ih,
                     const float* __restrict__ b_hh) {
    extern __shared__ unsigned smem[];
    unsigned* a_s = smem;
    unsigned* b_s = smem + E_B_OFF;
    int*      tok = (int*)(smem + E_TOK_OFF);

    const int tid  = threadIdx.x;
    const int nblk = blockIdx.x * 128;
    const int mblk = blockIdx.y * 128;

    if (tid < 128) tok[tid] = x_seq[mblk + tid];
    __syncthreads();

    const int w    = tid >> 5;
    const int lane = tid & 31;
    const int g    = lane >> 2;
    const int tig  = lane & 3;
    const int m0   = (w & 3) * 32;
    const int n0   = (w >> 2) * 64;

    const int lrow = tid >> 1;
    const int lc0  = (tid & 1) * 16;

    const unsigned sbase = (unsigned)__cvta_generic_to_shared(smem);

    float cfr[2][8][4];
#pragma unroll
    for (int mi = 0; mi < 2; mi++)
#pragma unroll
        for (int ni = 0; ni < 8; ni++)
#pragma unroll
            for (int q = 0; q < 4; q++) cfr[mi][ni][q] = 0.0f;

    const unsigned* asrc_row = g_emb_tf32 + (size_t)tok[lrow] * D_EMBED + lc0;
    const unsigned* bsrc_row = g_wih_tf32 + (size_t)(nblk + lrow) * D_EMBED + lc0;

    auto load_chunk = [&](int kc, int buf) {
        unsigned adst = sbase + (buf * EA_BUF + lrow * EA_STRIDE + lc0) * 4;
        const unsigned* asrc = asrc_row + kc * 32;
#pragma unroll
        for (int s = 0; s < 4; s++) cpa16(adst + s * 16, asrc + s * 4);
        unsigned bdst = sbase + (E_B_OFF + buf * EA_BUF + lrow * EA_STRIDE + lc0) * 4;
        const unsigned* bsrc = bsrc_row + kc * 32;
#pragma unroll
        for (int s = 0; s < 4; s++) cpa16(bdst + s * 16, bsrc + s * 4);
    };

    load_chunk(0, 0);
    cpa_commit();

    for (int kc = 0; kc < 16; kc++) {
        const int buf = kc & 1;
        if (kc + 1 < 16) {
            load_chunk(kc + 1, buf ^ 1);
            cpa_commit();
            cpa_wait1();
        } else {
            cpa_wait0();
        }
        __syncthreads();

        const unsigned* A = a_s + buf * EA_BUF;
        const unsigned* B = b_s + buf * EA_BUF;
#pragma unroll
        for (int k8 = 0; k8 < 32; k8 += 8) {
            unsigned afr[2][4];
#pragma unroll
            for (int mi = 0; mi < 2; mi++) {
                const int r = m0 + mi * 16 + g;
                afr[mi][0] = A[r * EA_STRIDE + k8 + tig];
                afr[mi][1] = A[(r + 8) * EA_STRIDE + k8 + tig];
                afr[mi][2] = A[r * EA_STRIDE + k8 + tig + 4];
                afr[mi][3] = A[(r + 8) * EA_STRIDE + k8 + tig + 4];
            }
#pragma unroll
            for (int ni = 0; ni < 8; ni++) {
                const int r = n0 + ni * 8 + g;
                unsigned b0 = B[r * EA_STRIDE + k8 + tig];
                unsigned b1 = B[r * EA_STRIDE + k8 + tig + 4];
#pragma unroll
                for (int mi = 0; mi < 2; mi++)
                    mma_tf32(cfr[mi][ni], afr[mi][0], afr[mi][1], afr[mi][2], afr[mi][3], b0, b1);
            }
        }
        __syncthreads();
    }

#pragma unroll
    for (int ni = 0; ni < 8; ni++) {
        const int col = nblk + n0 + ni * 8 + 2 * tig;
        const float bi0 = b_ih[col] + b_hh[col];
        const float bi1 = b_ih[col + 1] + b_hh[col + 1];
#pragma unroll
        for (int mi = 0; mi < 2; mi++) {
            const int row = mblk + m0 + mi * 16 + g;
            float2 v0 = make_float2(cfr[mi][ni][0] + bi0, cfr[mi][ni][1] + bi1);
            float2 v1 = make_float2(cfr[mi][ni][2] + bi0, cfr[mi][ni][3] + bi1);
            *(float2*)&g_xgates[(size_t)row * G4 + col] = v0;
            *(float2*)&g_xgates[(size_t)(row + 8) * G4 + col] = v1;
        }
    }
}

// ---------------------------------------------------------------------------
// Persistent LSTM recurrence, 128 CTAs x 512 threads (16 warps).
// Fragment-major layouts: every A-frag = 1 LDS.128, every B-frag = 1 LDS.64.
// h global buffer is stored PRE-PERMUTED: addr(m batch, k hidden) =
//   kc*8192 + oct*512 + rowblk*128 + lane*4 + word
//   kc=k>>7, oct=(k>>3)&15, rowblk=m>>4, lane=(m&7)*4+(k&3),
//   word=((m>>3)&1) + 2*((k>>2)&1)
// W resident smem similarly: kc*4096 + oct*256 + nb*64 + lane*2 + hi.
// Warps: 16 = 2(m: batch 32) x 8(K-split: 2 octets/chunk each).
// BK=128, 8 chunks, 2 smem buffers (sync-then-issue). gs: 8 K-slices folded
// into 4 slices over 2 phases. Flag-array grid barrier (st.release/ld.acquire).
// ---------------------------------------------------------------------------
#define PTHREADS  512
#define PW_WORDS  32768                   // W permuted: 8*4096
#define PA_OFF    PW_WORDS
#define PA_CH     8192                    // words per chunk buffer (64x128)
#define PGS_OFF   (PA_OFF + 2 * PA_CH)    // 49152
#define GS_SLICE  (64 * 33)               // 2112
#define P_WORDS   (PGS_OFF + 4 * GS_SLICE)   // 57600
#define P_SMEM_BYTES (P_WORDS * 4)           // 230400

__global__ __launch_bounds__(PTHREADS, 1)
void lstm_persistent(const float* __restrict__ W_hh,
                     float* __restrict__ outs, int out_size) {
    extern __shared__ unsigned smem[];
    unsigned* wp  = smem;
    unsigned* a_s = smem + PA_OFF;
    float*    gs  = (float*)(smem + PGS_OFF);

    const int tid  = threadIdx.x;
    const int bx   = blockIdx.x;
    const int j0   = bx * 8;
    const int w    = tid >> 5;
    const int lane = tid & 31;
    const int g    = lane >> 2;
    const int tig  = lane & 3;
    const int mt   = w & 1;              // batch half: rows mt*32..+31
    const int ks   = w >> 1;             // K-split 0..7 (octets 2ks, 2ks+1)

    // ---- W_hh tile: fp32 -> tf32, permuted fragment-major, resident ----
    for (int e = tid; e < 32 * D_HIDDEN; e += PTHREADS) {
        const int n = e >> 10;            // local gate-col 0..31
        const int k = e & 1023;
        const int grow = (n >> 3) * D_HIDDEN + j0 + (n & 7);
        const float v = W_hh[(size_t)grow * D_HIDDEN + k];
        const int kc  = k >> 7;
        const int oct = (k >> 3) & 15;
        const int hi  = (k >> 2) & 1;
        const int tg  = k & 3;
        const int nb  = n >> 3;
        const int gg  = n & 7;
        wp[kc * 4096 + oct * 256 + nb * 64 + (gg * 4 + tg) * 2 + hi] = f2tf32(v);
    }
    __syncthreads();

    // Cell mapping: 1 cell per thread
    const int cb_b = tid >> 3;     // batch 0..63
    const int cu   = tid & 7;      // unit 0..7
    float c_st = 0.0f;

    // Permuted write index for this thread's h value (k = j0+cu, m = cb_b)
    const unsigned hw_idx =
        (unsigned)((bx >> 4) * 8192 + (bx & 15) * 512 + (cb_b >> 4) * 128 +
                   ((cb_b & 7) * 4 + (cu & 3)) * 4 + ((cb_b >> 3) & 1) + 2 * (cu >> 2));

    const unsigned sbase = (unsigned)__cvta_generic_to_shared(smem);
    const unsigned adst0 = sbase + (unsigned)(PA_OFF + tid * 16) * 4;

    // x_gates prefetch for t=0
    float xi, xf, xg2, xo;
    {
        const float* p = g_xgates + (size_t)cb_b * G4 + j0 + cu;
        xi  = p[0];
        xf  = p[D_HIDDEN];
        xg2 = p[2 * D_HIDDEN];
        xo  = p[3 * D_HIDDEN];
    }

    for (int t = 0; t < T_STEPS; t++) {
        float cfr[2][4][4];
#pragma unroll
        for (int mi = 0; mi < 2; mi++)
#pragma unroll
            for (int na = 0; na < 4; na++)
#pragma unroll
                for (int q = 0; q < 4; q++) cfr[mi][na][q] = 0.0f;

        if (t > 0) {
            // Wait for all CTAs to publish h[t-1]
            if (tid < NCTA) {
                unsigned v;
                do {
                    asm volatile("ld.acquire.gpu.global.u32 %0, [%1];"
                                 : "=r"(v) : "l"(&g_flags[tid]));
                } while ((int)v < t);
            }
            __syncthreads();

            const unsigned* hsrc = g_h_perm[(t - 1) & 1] + tid * 16;
            // issue chunk 0 -> buf 0
#pragma unroll
            for (int s = 0; s < 4; s++) cpa16(adst0 + s * 16, hsrc + s * 4);
            cpa_commit();

#pragma unroll 1
            for (int kc = 0; kc < 8; kc++) {
                cpa_wait0();
                __syncthreads();
                if (kc + 1 < 8) {
                    const unsigned d = adst0 + (unsigned)(((kc + 1) & 1) * PA_CH) * 4;
                    const unsigned* s = hsrc + (kc + 1) * PA_CH;
#pragma unroll
                    for (int q = 0; q < 4; q++) cpa16(d + q * 16, s + q * 4);
                    cpa_commit();
                }

                const unsigned* A  = a_s + (kc & 1) * PA_CH;
                const unsigned* Wc = wp + kc * 4096;
#pragma unroll
                for (int oi = 0; oi < 2; oi++) {
                    const int oct = ks * 2 + oi;
                    uint4 af[2];
#pragma unroll
                    for (int mi = 0; mi < 2; mi++) {
                        const int rowblk = mt * 2 + mi;
                        af[mi] = *(const uint4*)(A + oct * 512 + rowblk * 128 + lane * 4);
                    }
                    const unsigned* wb = Wc + oct * 256 + lane * 2;
#pragma unroll
                    for (int na = 0; na < 4; na++) {
                        const uint2 bv = *(const uint2*)(wb + na * 64);
                        mma_tf32(cfr[0][na], af[0].x, af[0].y, af[0].z, af[0].w, bv.x, bv.y);
                        mma_tf32(cfr[1][na], af[1].x, af[1].y, af[1].z, af[1].w, bv.x, bv.y);
                    }
                }
            }
        }

        // gs reduction: 8 K-slices -> 4 slices in 2 phases
        {
            float* slice = gs + (ks >> 1) * GS_SLICE;
            const int ph = ks & 1;
            if (ph == 0) {
#pragma unroll
                for (int mi = 0; mi < 2; mi++) {
                    const int r0 = (mt * 32 + mi * 16 + g) * 33;
#pragma unroll
                    for (int na = 0; na < 4; na++) {
                        const int c = na * 8 + 2 * tig;
                        slice[r0 + c]            = cfr[mi][na][0];
                        slice[r0 + c + 1]        = cfr[mi][na][1];
                        slice[r0 + 8 * 33 + c]     = cfr[mi][na][2];
                        slice[r0 + 8 * 33 + c + 1] = cfr[mi][na][3];
                    }
                }
            }
            __syncthreads();
            if (ph == 1) {
#pragma unroll
                for (int mi = 0; mi < 2; mi++) {
                    const int r0 = (mt * 32 + mi * 16 + g) * 33;
#pragma unroll
                    for (int na = 0; na < 4; na++) {
                        const int c = na * 8 + 2 * tig;
                        slice[r0 + c]            += cfr[mi][na][0];
                        slice[r0 + c + 1]        += cfr[mi][na][1];
                        slice[r0 + 8 * 33 + c]     += cfr[mi][na][2];
                        slice[r0 + 8 * 33 + c + 1] += cfr[mi][na][3];
                    }
                }
            }
            __syncthreads();
        }

        // Fused elementwise
        float s0 = 0.0f, s1 = 0.0f, s2 = 0.0f, s3 = 0.0f;
#pragma unroll
        for (int q = 0; q < 4; q++) {
            const float* gp = gs + q * GS_SLICE + cb_b * 33 + cu;
            s0 += gp[0];
            s1 += gp[8];
            s2 += gp[16];
            s3 += gp[24];
        }
        const float vi = s0 + xi;
        const float vf = s1 + xf;
        const float vg = s2 + xg2;
        const float vo = s3 + xo;

        c_st = sigf(vf) * c_st + sigf(vi) * tanh_f(vg);
        const float hn = sigf(vo) * tanh_f(c_st);

        outs[(size_t)t * NH + (size_t)cb_b * D_HIDDEN + j0 + cu] = hn;
        g_h_perm[t & 1][hw_idx] = f2tf32(hn);

        if (t == T_STEPS - 1) {
            const size_t base = (size_t)T_STEPS * NH;
            if ((size_t)out_size >= base + 2 * (size_t)NH) {
                const size_t off = (size_t)cb_b * D_HIDDEN + j0 + cu;
                outs[base + off]      = hn;
                outs[base + NH + off] = c_st;
            }
        } else {
            __syncthreads();   // all h stores of this CTA done
            if (tid == 0) {
                asm volatile("st.release.gpu.global.u32 [%0], %1;"
                             :: "l"(&g_flags[bx]), "r"(t + 1));
            }
            // prefetch x_gates for t+1 (hides DRAM latency behind flag wait)
            const float* p = g_xgates + (size_t)(t + 1) * BATCH * G4
                           + (size_t)cb_b * G4 + j0 + cu;
            xi  = p[0];
            xf  = p[D_HIDDEN];
            xg2 = p[2 * D_HIDDEN];
            xo  = p[3 * D_HIDDEN];
        }
    }
}

// ---------------------------------------------------------------------------
extern "C" void kernel_launch(void* const* d_in, const int* in_sizes, int n_in,
                              void* d_out, int out_size)
{
    const int*   x_seq = (const int*)  d_in[0];
    const float* emb   = (const float*)d_in[1];
    const float* W_ih  = (const float*)d_in[2];
    const float* W_hh  = (const float*)d_in[3];
    const float* b_ih  = (const float*)d_in[4];
    const float* b_hh  = (const float*)d_in[5];
    float* out = (float*)d_out;

    cudaFuncSetAttribute(embed_gemm_tf32,
                         cudaFuncAttributeMaxDynamicSharedMemorySize, E_SMEM_BYTES);
    cudaFuncSetAttribute(lstm_persistent,
                         cudaFuncAttributeMaxDynamicSharedMemorySize, P_SMEM_BYTES);

    init_kernel<<<1, 128>>>();

    // Pre-convert embedding + W_ih to tf32 (W_hh converts inside persistent)
    {
        unsigned* demb; cudaGetSymbolAddress((void**)&demb, g_emb_tf32);
        unsigned* dwih; cudaGetSymbolAddress((void**)&dwih, g_wih_tf32);
        int n4e = (VOCAB * D_EMBED) / 4;
        int n4i = (G4 * D_EMBED) / 4;
        cvt_tf32_kernel<<<(n4e + 255) / 256, 256>>>((const float4*)emb,  (uint4*)demb, n4e);
        cvt_tf32_kernel<<<(n4i + 255) / 256, 256>>>((const float4*)W_ih, (uint4*)dwih, n4i);
    }

    dim3 eg(G4 / 128, (T_STEPS * BATCH) / 128);   // (32, 128)
    embed_gemm_tf32<<<eg, 256, E_SMEM_BYTES>>>(x_seq, b_ih, b_hh);

    lstm_persistent<<<NCTA, PTHREADS, P_SMEM_BYTES>>>(W_hh, out, out_size);
}

// round 8
// speedup vs baseline: 1.5701x; 1.5701x over previous
#include <cuda_runtime.h>
#include <math.h>
#include <stdint.h>

// Problem constants
#define T_STEPS  256
#define BATCH    64
#define VOCAB    32000
#define D_EMBED  512
#define D_HIDDEN 1024
#define G4       (4 * D_HIDDEN)          // 4096
#define NH       (BATCH * D_HIDDEN)      // 65536
#define NCTA     128

// Scratch
__device__ float    g_xgates[(size_t)T_STEPS * BATCH * G4];   // 256 MiB fp32
__device__ unsigned g_emb_tf32[(size_t)VOCAB * D_EMBED];      // tf32 bits
__device__ unsigned g_wih_tf32[(size_t)G4 * D_EMBED];
__device__ unsigned g_h_perm[2][NH];     // ping-pong h, fragment-major tf32
__device__ unsigned g_bar_count;
__device__ volatile unsigned g_bar_gen;

// ---------------------------------------------------------------------------
// Helpers
// ---------------------------------------------------------------------------
__device__ __forceinline__ unsigned f2tf32(float f) {
    unsigned u;
    asm("cvt.rna.tf32.f32 %0, %1;" : "=r"(u) : "f"(f));
    return u;
}

__device__ __forceinline__ void cpa16(unsigned dst_s, const void* src) {
    asm volatile("cp.async.cg.shared.global [%0], [%1], 16;" :: "r"(dst_s), "l"(src));
}
__device__ __forceinline__ void cpa_commit() {
    asm volatile("cp.async.commit_group;");
}
__device__ __forceinline__ void cpa_wait1() {
    asm volatile("cp.async.wait_group 1;");
}
__device__ __forceinline__ void cpa_wait0() {
    asm volatile("cp.async.wait_group 0;");
}

__device__ __forceinline__ void mma_tf32(float c[4],
                                         unsigned a0, unsigned a1, unsigned a2, unsigned a3,
                                         unsigned b0, unsigned b1) {
    asm volatile(
        "mma.sync.aligned.m16n8k8.row.col.f32.tf32.tf32.f32 "
        "{%0,%1,%2,%3}, {%4,%5,%6,%7}, {%8,%9}, {%0,%1,%2,%3};"
        : "+f"(c[0]), "+f"(c[1]), "+f"(c[2]), "+f"(c[3])
        : "r"(a0), "r"(a1), "r"(a2), "r"(a3), "r"(b0), "r"(b1));
}

// Fast sigmoid/tanh via MUFU; abs err ~1e-6, safe vs 1e-3 threshold.
__device__ __forceinline__ float sigf(float x) {
    return __fdividef(1.0f, 1.0f + __expf(-x));
}
__device__ __forceinline__ float tanh_f(float x) {
    return 2.0f * __fdividef(1.0f, 1.0f + __expf(-2.0f * x)) - 1.0f;
}

// ---------------------------------------------------------------------------
// Init: reset barrier state (fresh every launch for graph replay)
// ---------------------------------------------------------------------------
__global__ void init_kernel() {
    g_bar_count = 0;
    g_bar_gen = 0;
}

// ---------------------------------------------------------------------------
// fp32 -> tf32 (rna) bulk convert, vectorized x4
// ---------------------------------------------------------------------------
__global__ void cvt_tf32_kernel(const float4* __restrict__ src,
                                uint4* __restrict__ dst, int n4) {
    int i = blockIdx.x * blockDim.x + threadIdx.x;
    if (i < n4) {
        float4 v = src[i];
        uint4 o;
        o.x = f2tf32(v.x); o.y = f2tf32(v.y);
        o.z = f2tf32(v.z); o.w = f2tf32(v.w);
        dst[i] = o;
    }
}

// ---------------------------------------------------------------------------
// Embed gather + input GEMM (tf32 tensor cores)  [unchanged — passing]
// ---------------------------------------------------------------------------
#define EA_STRIDE 36
#define EA_BUF    (128 * EA_STRIDE)
#define E_B_OFF   (2 * EA_BUF)
#define E_TOK_OFF (4 * EA_BUF)
#define E_SMEM_WORDS (E_TOK_OFF + 128)
#define E_SMEM_BYTES (E_SMEM_WORDS * 4)

__global__ __launch_bounds__(256, 2)
void embed_gemm_tf32(const int* __restrict__ x_seq,
                     const float* __restrict__ b_ih,
                     const float* __restrict__ b_hh) {
    extern __shared__ unsigned smem[];
    unsigned* a_s = smem;
    unsigned* b_s = smem + E_B_OFF;
    int*      tok = (int*)(smem + E_TOK_OFF);

    const int tid  = threadIdx.x;
    const int nblk = blockIdx.x * 128;
    const int mblk = blockIdx.y * 128;

    if (tid < 128) tok[tid] = x_seq[mblk + tid];
    __syncthreads();

    const int w    = tid >> 5;
    const int lane = tid & 31;
    const int g    = lane >> 2;
    const int tig  = lane & 3;
    const int m0   = (w & 3) * 32;
    const int n0   = (w >> 2) * 64;

    const int lrow = tid >> 1;
    const int lc0  = (tid & 1) * 16;

    const unsigned sbase = (unsigned)__cvta_generic_to_shared(smem);

    float cfr[2][8][4];
#pragma unroll
    for (int mi = 0; mi < 2; mi++)
#pragma unroll
        for (int ni = 0; ni < 8; ni++)
#pragma unroll
            for (int q = 0; q < 4; q++) cfr[mi][ni][q] = 0.0f;

    const unsigned* asrc_row = g_emb_tf32 + (size_t)tok[lrow] * D_EMBED + lc0;
    const unsigned* bsrc_row = g_wih_tf32 + (size_t)(nblk + lrow) * D_EMBED + lc0;

    auto load_chunk = [&](int kc, int buf) {
        unsigned adst = sbase + (buf * EA_BUF + lrow * EA_STRIDE + lc0) * 4;
        const unsigned* asrc = asrc_row + kc * 32;
#pragma unroll
        for (int s = 0; s < 4; s++) cpa16(adst + s * 16, asrc + s * 4);
        unsigned bdst = sbase + (E_B_OFF + buf * EA_BUF + lrow * EA_STRIDE + lc0) * 4;
        const unsigned* bsrc = bsrc_row + kc * 32;
#pragma unroll
        for (int s = 0; s < 4; s++) cpa16(bdst + s * 16, bsrc + s * 4);
    };

    load_chunk(0, 0);
    cpa_commit();

    for (int kc = 0; kc < 16; kc++) {
        const int buf = kc & 1;
        if (kc + 1 < 16) {
            load_chunk(kc + 1, buf ^ 1);
            cpa_commit();
            cpa_wait1();
        } else {
            cpa_wait0();
        }
        __syncthreads();

        const unsigned* A = a_s + buf * EA_BUF;
        const unsigned* B = b_s + buf * EA_BUF;
#pragma unroll
        for (int k8 = 0; k8 < 32; k8 += 8) {
            unsigned afr[2][4];
#pragma unroll
            for (int mi = 0; mi < 2; mi++) {
                const int r = m0 + mi * 16 + g;
                afr[mi][0] = A[r * EA_STRIDE + k8 + tig];
                afr[mi][1] = A[(r + 8) * EA_STRIDE + k8 + tig];
                afr[mi][2] = A[r * EA_STRIDE + k8 + tig + 4];
                afr[mi][3] = A[(r + 8) * EA_STRIDE + k8 + tig + 4];
            }
#pragma unroll
            for (int ni = 0; ni < 8; ni++) {
                const int r = n0 + ni * 8 + g;
                unsigned b0 = B[r * EA_STRIDE + k8 + tig];
                unsigned b1 = B[r * EA_STRIDE + k8 + tig + 4];
#pragma unroll
                for (int mi = 0; mi < 2; mi++)
                    mma_tf32(cfr[mi][ni], afr[mi][0], afr[mi][1], afr[mi][2], afr[mi][3], b0, b1);
            }
        }
        __syncthreads();
    }

#pragma unroll
    for (int ni = 0; ni < 8; ni++) {
        const int col = nblk + n0 + ni * 8 + 2 * tig;
        const float bi0 = b_ih[col] + b_hh[col];
        const float bi1 = b_ih[col + 1] + b_hh[col + 1];
#pragma unroll
        for (int mi = 0; mi < 2; mi++) {
            const int row = mblk + m0 + mi * 16 + g;
            float2 v0 = make_float2(cfr[mi][ni][0] + bi0, cfr[mi][ni][1] + bi1);
            float2 v1 = make_float2(cfr[mi][ni][2] + bi0, cfr[mi][ni][3] + bi1);
            *(float2*)&g_xgates[(size_t)row * G4 + col] = v0;
            *(float2*)&g_xgates[(size_t)(row + 8) * G4 + col] = v1;
        }
    }
}

// ---------------------------------------------------------------------------
// Persistent LSTM recurrence, 128 CTAs x 512 threads (16 warps).
// R6 skeleton (3-buffer depth-2 cp.async, BK=64, atomic+gen barrier,
// 4 gs K-slices summed in the elementwise phase) + fragment-major layouts:
//   h chunk kc (64 batch x 64 k):  kc*4096 + oct*512 + rowblk*128 + lane*4
//     + word,  oct=(k>>3)&7, rowblk=m>>4, lane=(m&7)*4+(k&3),
//     word=((m>>3)&1) + 2*((k>>2)&1)   -> A-frag = ONE LDS.128
//   W resident:  kc*2048 + oct*256 + nb*64 + ((n&7)*4+(k&3))*2 + ((k>>2)&1)
//     -> B-frag = ONE LDS.64.  Both conflict-free, no padding.
// Warps: 16 = 2(m half) x 2(n half) x 4(K-split: 2 octets each).
// ---------------------------------------------------------------------------
#define PTHREADS  512
#define PW_WORDS  32768                   // W permuted: 16 chunks * 2048
#define PA_OFF    PW_WORDS
#define PA_CH     4096                    // words per chunk buffer (64x64)
#define PGS_OFF   (PA_OFF + 3 * PA_CH)    // 45056
#define GS_SLICE  (64 * 33)               // 2112
#define P_WORDS   (PGS_OFF + 4 * GS_SLICE)   // 53504
#define P_SMEM_BYTES (P_WORDS * 4)           // 214016

__device__ __forceinline__ void grid_barrier(int target) {
    __syncthreads();
    if (threadIdx.x == 0) {
        __threadfence();
        unsigned old = atomicAdd(&g_bar_count, 1u);
        if (old == NCTA - 1) {
            g_bar_count = 0;
            __threadfence();
            g_bar_gen = (unsigned)target;
        } else {
            while (g_bar_gen < (unsigned)target) { }
        }
        __threadfence();
    }
    __syncthreads();
}

__global__ __launch_bounds__(PTHREADS, 1)
void lstm_persistent(const float* __restrict__ W_hh,
                     float* __restrict__ outs, int out_size) {
    extern __shared__ unsigned smem[];
    unsigned* wp  = smem;
    unsigned* a_s = smem + PA_OFF;
    float*    gs  = (float*)(smem + PGS_OFF);

    const int tid  = threadIdx.x;
    const int bx   = blockIdx.x;
    const int j0   = bx * 8;
    const int w    = tid >> 5;
    const int lane = tid & 31;
    const int g    = lane >> 2;
    const int tig  = lane & 3;
    const int mt   = w & 1;              // batch half: rowblocks mt*2, mt*2+1
    const int nt   = (w >> 1) & 1;       // n half: nb nt*2, nt*2+1
    const int ks   = w >> 2;             // K-split 0..3 (octets 2ks, 2ks+1)

    // ---- W_hh tile: fp32 -> tf32, permuted fragment-major, resident ----
    for (int e = tid; e < 32 * D_HIDDEN; e += PTHREADS) {
        const int n = e >> 10;            // local gate-col 0..31
        const int k = e & 1023;
        const int grow = (n >> 3) * D_HIDDEN + j0 + (n & 7);
        const float v = W_hh[(size_t)grow * D_HIDDEN + k];
        const int kc  = k >> 6;
        const int oct = (k >> 3) & 7;
        const int khi = (k >> 2) & 1;
        const int tg  = k & 3;
        wp[kc * 2048 + oct * 256 + (n >> 3) * 64 + ((n & 7) * 4 + tg) * 2 + khi]
            = f2tf32(v);
    }
    __syncthreads();

    // Cell mapping: 1 cell per thread
    const int cb_b = tid >> 3;     // batch 0..63
    const int cu   = tid & 7;      // unit 0..7
    float c_st = 0.0f;

    // Permuted write index for this thread's h value (k = j0+cu, m = cb_b):
    // kc = bx>>3, oct = bx&7 (cu<8), rowblk = cb_b>>4
    const unsigned hw_idx =
        (unsigned)((bx >> 3) * 4096 + (bx & 7) * 512 + (cb_b >> 4) * 128 +
                   ((cb_b & 7) * 4 + (cu & 3)) * 4 +
                   ((cb_b >> 3) & 1) + 2 * (cu >> 2));

    const unsigned sbase = (unsigned)__cvta_generic_to_shared(smem);
    const unsigned adst0 = sbase + (unsigned)(PA_OFF + tid * 8) * 4;

    // x_gates prefetch for t=0
    float xi, xf, xg2, xo;
    {
        const float* p = g_xgates + (size_t)cb_b * G4 + j0 + cu;
        xi  = p[0];
        xf  = p[D_HIDDEN];
        xg2 = p[2 * D_HIDDEN];
        xo  = p[3 * D_HIDDEN];
    }

    for (int t = 0; t < T_STEPS; t++) {
        float cfr[2][2][4];
#pragma unroll
        for (int mi = 0; mi < 2; mi++)
#pragma unroll
            for (int na = 0; na < 2; na++)
#pragma unroll
                for (int q = 0; q < 4; q++) cfr[mi][na][q] = 0.0f;

        if (t > 0) {
            const unsigned* hbase = g_h_perm[(t - 1) & 1] + tid * 8;
            // issue chunks 0, 1 (depth-2)
            cpa16(adst0, hbase);
            cpa16(adst0 + 16, hbase + 4);
            cpa_commit();
            {
                const unsigned d1 = adst0 + (unsigned)PA_CH * 4;
                cpa16(d1, hbase + PA_CH);
                cpa16(d1 + 16, hbase + PA_CH + 4);
                cpa_commit();
            }

#pragma unroll 1
            for (int kc = 0; kc < 16; kc++) {
                if (kc < 15) cpa_wait1(); else cpa_wait0();
                __syncthreads();
                if (kc + 2 < 16) {
                    const unsigned d = adst0 + (unsigned)(((kc + 2) % 3) * PA_CH) * 4;
                    const unsigned* s = hbase + (kc + 2) * PA_CH;
                    cpa16(d, s);
                    cpa16(d + 16, s + 4);
                    cpa_commit();
                }

                const unsigned* A  = a_s + (kc % 3) * PA_CH;
                const unsigned* Wc = wp + kc * 2048;
#pragma unroll
                for (int oi = 0; oi < 2; oi++) {
                    const int oct = ks * 2 + oi;
                    uint4 af[2];
#pragma unroll
                    for (int mi = 0; mi < 2; mi++)
                        af[mi] = *(const uint4*)(A + oct * 512 + (mt * 2 + mi) * 128 + lane * 4);
                    const unsigned* wb = Wc + oct * 256 + lane * 2;
#pragma unroll
                    for (int na = 0; na < 2; na++) {
                        const uint2 bv = *(const uint2*)(wb + (nt * 2 + na) * 64);
                        mma_tf32(cfr[0][na], af[0].x, af[0].y, af[0].z, af[0].w, bv.x, bv.y);
                        mma_tf32(cfr[1][na], af[1].x, af[1].y, af[1].z, af[1].w, bv.x, bv.y);
                    }
                }
            }
        }

        // Write K-split partials to this group's gs slice
        {
            float* slice = gs + ks * GS_SLICE;
#pragma unroll
            for (int mi = 0; mi < 2; mi++) {
                const int r0 = (mt * 32 + mi * 16 + g) * 33;
#pragma unroll
                for (int na = 0; na < 2; na++) {
                    const int c = nt * 16 + na * 8 + 2 * tig;
                    slice[r0 + c]              = cfr[mi][na][0];
                    slice[r0 + c + 1]          = cfr[mi][na][1];
                    slice[r0 + 8 * 33 + c]     = cfr[mi][na][2];
                    slice[r0 + 8 * 33 + c + 1] = cfr[mi][na][3];
                }
            }
        }
        __syncthreads();

        // Fused elementwise: sum 4 slices + x_gates, activations, cell update
        float s0 = 0.0f, s1 = 0.0f, s2 = 0.0f, s3 = 0.0f;
#pragma unroll
        for (int q = 0; q < 4; q++) {
            const float* gp = gs + q * GS_SLICE + cb_b * 33 + cu;
            s0 += gp[0];
            s1 += gp[8];
            s2 += gp[16];
            s3 += gp[24];
        }
        const float vi = s0 + xi;
        const float vf = s1 + xf;
        const float vg = s2 + xg2;
        const float vo = s3 + xo;

        c_st = sigf(vf) * c_st + sigf(vi) * tanh_f(vg);
        const float hn = sigf(vo) * tanh_f(c_st);

        outs[(size_t)t * NH + (size_t)cb_b * D_HIDDEN + j0 + cu] = hn;
        g_h_perm[t & 1][hw_idx] = f2tf32(hn);

        if (t == T_STEPS - 1) {
            const size_t base = (size_t)T_STEPS * NH;
            if ((size_t)out_size >= base + 2 * (size_t)NH) {
                const size_t off = (size_t)cb_b * D_HIDDEN + j0 + cu;
                outs[base + off]      = hn;
                outs[base + NH + off] = c_st;
            }
        } else {
            // prefetch x_gates for t+1 (hides DRAM latency behind the barrier)
            const float* p = g_xgates + (size_t)(t + 1) * BATCH * G4
                           + (size_t)cb_b * G4 + j0 + cu;
            xi  = p[0];
            xf  = p[D_HIDDEN];
            xg2 = p[2 * D_HIDDEN];
            xo  = p[3 * D_HIDDEN];
            grid_barrier(t + 1);
        }
    }
}

// ---------------------------------------------------------------------------
extern "C" void kernel_launch(void* const* d_in, const int* in_sizes, int n_in,
                              void* d_out, int out_size)
{
    const int*   x_seq = (const int*)  d_in[0];
    const float* emb   = (const float*)d_in[1];
    const float* W_ih  = (const float*)d_in[2];
    const float* W_hh  = (const float*)d_in[3];
    const float* b_ih  = (const float*)d_in[4];
    const float* b_hh  = (const float*)d_in[5];
    float* out = (float*)d_out;

    cudaFuncSetAttribute(embed_gemm_tf32,
                         cudaFuncAttributeMaxDynamicSharedMemorySize, E_SMEM_BYTES);
    cudaFuncSetAttribute(lstm_persistent,
                         cudaFuncAttributeMaxDynamicSharedMemorySize, P_SMEM_BYTES);

    init_kernel<<<1, 1>>>();

    // Pre-convert embedding + W_ih to tf32 (W_hh converts inside persistent)
    {
        unsigned* demb; cudaGetSymbolAddress((void**)&demb, g_emb_tf32);
        unsigned* dwih; cudaGetSymbolAddress((void**)&dwih, g_wih_tf32);
        int n4e = (VOCAB * D_EMBED) / 4;
        int n4i = (G4 * D_EMBED) / 4;
        cvt_tf32_kernel<<<(n4e + 255) / 256, 256>>>((const float4*)emb,  (uint4*)demb, n4e);
        cvt_tf32_kernel<<<(n4i + 255) / 256, 256>>>((const float4*)W_ih, (uint4*)dwih, n4i);
    }

    dim3 eg(G4 / 128, (T_STEPS * BATCH) / 128);   // (32, 128)
    embed_gemm_tf32<<<eg, 256, E_SMEM_BYTES>>>(x_seq, b_ih, b_hh);

    lstm_persistent<<<NCTA, PTHREADS, P_SMEM_BYTES>>>(W_hh, out, out_size);
}

// round 9
// speedup vs baseline: 2.4625x; 1.5684x over previous
#include <cuda_runtime.h>
#include <cuda_fp16.h>
#include <math.h>
#include <stdint.h>

// Problem constants
#define T_STEPS  256
#define BATCH    64
#define VOCAB    32000
#define D_EMBED  512
#define D_HIDDEN 1024
#define G4       (4 * D_HIDDEN)          // 4096
#define NH       (BATCH * D_HIDDEN)      // 65536
#define NCTA     128

// Scratch
__device__ float    g_xgates[(size_t)T_STEPS * BATCH * G4];   // 256 MiB fp32
__device__ unsigned g_emb_f16[(size_t)VOCAB * D_EMBED / 2];   // packed fp16x2
__device__ unsigned g_wih_f16[(size_t)G4 * D_EMBED / 2];
__device__ unsigned g_h_perm[2][NH / 2];  // ping-pong h, fragment-major fp16
__device__ unsigned g_bar_count;
__device__ volatile unsigned g_bar_gen;

// ---------------------------------------------------------------------------
// Helpers
// ---------------------------------------------------------------------------
__device__ __forceinline__ unsigned pack_f16x2(float lo, float hi) {
    __half2 h2 = __floats2half2_rn(lo, hi);   // lo -> .x (low 16), hi -> .y
    return *(unsigned*)&h2;
}

__device__ __forceinline__ void cpa16(unsigned dst_s, const void* src) {
    asm volatile("cp.async.cg.shared.global [%0], [%1], 16;" :: "r"(dst_s), "l"(src));
}
__device__ __forceinline__ void cpa_commit() {
    asm volatile("cp.async.commit_group;");
}
__device__ __forceinline__ void cpa_wait1() {
    asm volatile("cp.async.wait_group 1;");
}
__device__ __forceinline__ void cpa_wait0() {
    asm volatile("cp.async.wait_group 0;");
}

// m16n8k16 fp16 MMA, fp32 accumulate
__device__ __forceinline__ void mma_f16(float c[4],
                                        unsigned a0, unsigned a1, unsigned a2, unsigned a3,
                                        unsigned b0, unsigned b1) {
    asm volatile(
        "mma.sync.aligned.m16n8k16.row.col.f32.f16.f16.f32 "
        "{%0,%1,%2,%3}, {%4,%5,%6,%7}, {%8,%9}, {%0,%1,%2,%3};"
        : "+f"(c[0]), "+f"(c[1]), "+f"(c[2]), "+f"(c[3])
        : "r"(a0), "r"(a1), "r"(a2), "r"(a3), "r"(b0), "r"(b1));
}

// Fast sigmoid/tanh via MUFU; abs err ~1e-6, safe vs 1e-3 threshold.
__device__ __forceinline__ float sigf(float x) {
    return __fdividef(1.0f, 1.0f + __expf(-x));
}
__device__ __forceinline__ float tanh_f(float x) {
    return 2.0f * __fdividef(1.0f, 1.0f + __expf(-2.0f * x)) - 1.0f;
}

// ---------------------------------------------------------------------------
// Init: reset barrier state (fresh every launch for graph replay)
// ---------------------------------------------------------------------------
__global__ void init_kernel() {
    g_bar_count = 0;
    g_bar_gen = 0;
}

// ---------------------------------------------------------------------------
// fp32 -> fp16x2 bulk convert (4 floats -> 2 packed words per thread)
// ---------------------------------------------------------------------------
__global__ void cvt_f16_kernel(const float4* __restrict__ src,
                               uint2* __restrict__ dst, int n4) {
    int i = blockIdx.x * blockDim.x + threadIdx.x;
    if (i < n4) {
        float4 v = src[i];
        uint2 o;
        o.x = pack_f16x2(v.x, v.y);
        o.y = pack_f16x2(v.z, v.w);
        dst[i] = o;
    }
}

// ---------------------------------------------------------------------------
// Embed gather + input GEMM (fp16 tensor cores, fp32 accum):
//   x_gates[m][n] = sum_k emb[x_seq[m]][k] * W_ih[n][k] + b_ih[n] + b_hh[n]
// M=16384, N=4096, K=512. CTA tile 128x128, BK=32 (16 words), 256 threads,
// warp tile 32x64 (2 k16-atoms x 2 mi x 8 ni). 2-stage cp.async pipeline.
// Rows packed fp16x2 (16 data words + 4 pad = stride 20, conflict-free).
// ---------------------------------------------------------------------------
#define EA_STRIDE 20
#define EA_BUF    (128 * EA_STRIDE)      // 2560 words
#define E_B_OFF   (2 * EA_BUF)           // 5120
#define E_TOK_OFF (4 * EA_BUF)           // 10240
#define E_SMEM_WORDS (E_TOK_OFF + 128)   // 10368
#define E_SMEM_BYTES (E_SMEM_WORDS * 4)  // 41472

__global__ __launch_bounds__(256, 2)
void embed_gemm_f16(const int* __restrict__ x_seq,
                    const float* __restrict__ b_ih,
                    const float* __restrict__ b_hh) {
    extern __shared__ unsigned smem[];
    unsigned* a_s = smem;
    unsigned* b_s = smem + E_B_OFF;
    int*      tok = (int*)(smem + E_TOK_OFF);

    const int tid  = threadIdx.x;
    const int nblk = blockIdx.x * 128;
    const int mblk = blockIdx.y * 128;

    if (tid < 128) tok[tid] = x_seq[mblk + tid];
    __syncthreads();

    const int w    = tid >> 5;
    const int lane = tid & 31;
    const int g    = lane >> 2;
    const int tig  = lane & 3;
    const int m0   = (w & 3) * 32;
    const int n0   = (w >> 2) * 64;

    const int lrow = tid >> 1;           // 0..127
    const int lc0  = (tid & 1) * 8;      // word offset 0 or 8

    const unsigned sbase = (unsigned)__cvta_generic_to_shared(smem);

    float cfr[2][8][4];
#pragma unroll
    for (int mi = 0; mi < 2; mi++)
#pragma unroll
        for (int ni = 0; ni < 8; ni++)
#pragma unroll
            for (int q = 0; q < 4; q++) cfr[mi][ni][q] = 0.0f;

    // fp16 rows: emb row = 256 words, chunk = 16 words
    const unsigned* asrc_row = g_emb_f16 + (size_t)tok[lrow] * (D_EMBED / 2) + lc0;
    const unsigned* bsrc_row = g_wih_f16 + (size_t)(nblk + lrow) * (D_EMBED / 2) + lc0;

    auto load_chunk = [&](int kc, int buf) {
        unsigned adst = sbase + (buf * EA_BUF + lrow * EA_STRIDE + lc0) * 4;
        const unsigned* asrc = asrc_row + kc * 16;
        cpa16(adst, asrc);
        cpa16(adst + 16, asrc + 4);
        unsigned bdst = sbase + (E_B_OFF + buf * EA_BUF + lrow * EA_STRIDE + lc0) * 4;
        const unsigned* bsrc = bsrc_row + kc * 16;
        cpa16(bdst, bsrc);
        cpa16(bdst + 16, bsrc + 4);
    };

    load_chunk(0, 0);
    cpa_commit();

    for (int kc = 0; kc < 16; kc++) {
        const int buf = kc & 1;
        if (kc + 1 < 16) {
            load_chunk(kc + 1, buf ^ 1);
            cpa_commit();
            cpa_wait1();
        } else {
            cpa_wait0();
        }
        __syncthreads();

        const unsigned* A = a_s + buf * EA_BUF;
        const unsigned* B = b_s + buf * EA_BUF;
#pragma unroll
        for (int at = 0; at < 2; at++) {     // 2 k16-atoms per 32-k chunk
            const int kw0 = at * 8;
            unsigned afr[2][4];
#pragma unroll
            for (int mi = 0; mi < 2; mi++) {
                const int r = m0 + mi * 16 + g;
                afr[mi][0] = A[r * EA_STRIDE + kw0 + tig];
                afr[mi][1] = A[(r + 8) * EA_STRIDE + kw0 + tig];
                afr[mi][2] = A[r * EA_STRIDE + kw0 + tig + 4];
                afr[mi][3] = A[(r + 8) * EA_STRIDE + kw0 + tig + 4];
            }
#pragma unroll
            for (int ni = 0; ni < 8; ni++) {
                const int r = n0 + ni * 8 + g;
                unsigned b0 = B[r * EA_STRIDE + kw0 + tig];
                unsigned b1 = B[r * EA_STRIDE + kw0 + tig + 4];
#pragma unroll
                for (int mi = 0; mi < 2; mi++)
                    mma_f16(cfr[mi][ni], afr[mi][0], afr[mi][1], afr[mi][2], afr[mi][3], b0, b1);
            }
        }
        __syncthreads();
    }

#pragma unroll
    for (int ni = 0; ni < 8; ni++) {
        const int col = nblk + n0 + ni * 8 + 2 * tig;
        const float bi0 = b_ih[col] + b_hh[col];
        const float bi1 = b_ih[col + 1] + b_hh[col + 1];
#pragma unroll
        for (int mi = 0; mi < 2; mi++) {
            const int row = mblk + m0 + mi * 16 + g;
            float2 v0 = make_float2(cfr[mi][ni][0] + bi0, cfr[mi][ni][1] + bi1);
            float2 v1 = make_float2(cfr[mi][ni][2] + bi0, cfr[mi][ni][3] + bi1);
            *(float2*)&g_xgates[(size_t)row * G4 + col] = v0;
            *(float2*)&g_xgates[(size_t)(row + 8) * G4 + col] = v1;
        }
    }
}

// ---------------------------------------------------------------------------
// Persistent LSTM recurrence, 128 CTAs x 512 threads (16 warps).
// R8 skeleton (3-buffer depth-2 cp.async, atomic+gen barrier, 4 gs K-slices)
// with fp16 m16n8k16 and fragment-major fp16 layouts:
//   h chunk kc (64 batch x 128 k):  word = kc*4096 + hex*512 + rowblk*128
//     + lane*4 + wrd,  hex=(k>>4)&7, rowblk=m>>4, lane=(m&7)*4+((k>>1)&3),
//     wrd=((m>>3)&1)+2*((k>>3)&1), half=k&1   -> A-frag = ONE LDS.128
//   W resident: word = kcw*2048 + hex*256 + nb*64 + ((n&7)*4+((k>>1)&3))*2
//     + ((k>>3)&1), half=k&1                   -> B-frag = ONE LDS.64
// Warps: 16 = 2(m half) x 2(n half) x 4(K-split: 2 hexes/chunk each).
// 8 chunks of BK=128 per step.
// ---------------------------------------------------------------------------
#define PTHREADS  512
#define PW_WORDS  16384                   // W permuted: 8 chunks * 2048
#define PA_OFF    PW_WORDS
#define PA_CH     4096                    // words per chunk buffer (64x128 fp16)
#define PGS_OFF   (PA_OFF + 3 * PA_CH)    // 28672
#define GS_SLICE  (64 * 33)               // 2112
#define P_WORDS   (PGS_OFF + 4 * GS_SLICE)   // 37120
#define P_SMEM_BYTES (P_WORDS * 4)           // 148480

__device__ __forceinline__ void grid_barrier(int target) {
    __syncthreads();
    if (threadIdx.x == 0) {
        __threadfence();
        unsigned old = atomicAdd(&g_bar_count, 1u);
        if (old == NCTA - 1) {
            g_bar_count = 0;
            __threadfence();
            g_bar_gen = (unsigned)target;
        } else {
            while (g_bar_gen < (unsigned)target) { }
        }
        __threadfence();
    }
    __syncthreads();
}

__global__ __launch_bounds__(PTHREADS, 1)
void lstm_persistent(const float* __restrict__ W_hh,
                     float* __restrict__ outs, int out_size) {
    extern __shared__ unsigned smem[];
    unsigned* wp  = smem;
    unsigned* a_s = smem + PA_OFF;
    float*    gs  = (float*)(smem + PGS_OFF);

    const int tid  = threadIdx.x;
    const int bx   = blockIdx.x;
    const int j0   = bx * 8;
    const int w    = tid >> 5;
    const int lane = tid & 31;
    const int g    = lane >> 2;
    const int tig  = lane & 3;
    const int mt   = w & 1;              // batch half: rowblocks mt*2, mt*2+1
    const int nt   = (w >> 1) & 1;       // n half: nb nt*2, nt*2+1
    const int ks   = w >> 2;             // K-split 0..3 (hexes 2ks, 2ks+1)

    // ---- W_hh tile: fp32 -> fp16, permuted fragment-major, resident ----
    {
        unsigned short* wph = (unsigned short*)wp;
        for (int e = tid; e < 32 * D_HIDDEN; e += PTHREADS) {
            const int n = e >> 10;            // local gate-col 0..31
            const int k = e & 1023;
            const int grow = (n >> 3) * D_HIDDEN + j0 + (n & 7);
            const float v = W_hh[(size_t)grow * D_HIDDEN + k];
            const int kcw = k >> 7;
            const int hex = (k >> 4) & 7;
            const unsigned word = kcw * 2048 + hex * 256 + (n >> 3) * 64 +
                                  ((n & 7) * 4 + ((k >> 1) & 3)) * 2 + ((k >> 3) & 1);
            wph[word * 2 + (k & 1)] = __half_as_ushort(__float2half_rn(v));
        }
    }
    __syncthreads();

    // Cell mapping: 1 cell per thread
    const int cb_b = tid >> 3;     // batch 0..63
    const int cu   = tid & 7;      // unit 0..7
    float c_st = 0.0f;

    // Permuted write index (word) for this thread's h value (k=j0+cu, m=cb_b)
    const unsigned hw_word =
        (unsigned)((bx >> 4) * 4096 + ((bx >> 1) & 7) * 512 + (cb_b >> 4) * 128 +
                   ((cb_b & 7) * 4 + (cu >> 1)) * 4 +
                   ((cb_b >> 3) & 1) + 2 * (bx & 1));
    const unsigned hw_half = cu & 1;

    const unsigned sbase = (unsigned)__cvta_generic_to_shared(smem);
    const unsigned adst0 = sbase + (unsigned)(PA_OFF + tid * 8) * 4;

    // x_gates prefetch for t=0
    float xi, xf, xg2, xo;
    {
        const float* p = g_xgates + (size_t)cb_b * G4 + j0 + cu;
        xi  = p[0];
        xf  = p[D_HIDDEN];
        xg2 = p[2 * D_HIDDEN];
        xo  = p[3 * D_HIDDEN];
    }

    for (int t = 0; t < T_STEPS; t++) {
        float cfr[2][2][4];
#pragma unroll
        for (int mi = 0; mi < 2; mi++)
#pragma unroll
            for (int na = 0; na < 2; na++)
#pragma unroll
                for (int q = 0; q < 4; q++) cfr[mi][na][q] = 0.0f;

        if (t > 0) {
            const unsigned* hbase = g_h_perm[(t - 1) & 1] + tid * 8;
            // issue chunks 0, 1 (depth-2)
            cpa16(adst0, hbase);
            cpa16(adst0 + 16, hbase + 4);
            cpa_commit();
            {
                const unsigned d1 = adst0 + (unsigned)PA_CH * 4;
                cpa16(d1, hbase + PA_CH);
                cpa16(d1 + 16, hbase + PA_CH + 4);
                cpa_commit();
            }

#pragma unroll 1
            for (int kc = 0; kc < 8; kc++) {
                if (kc < 7) cpa_wait1(); else cpa_wait0();
                __syncthreads();
                if (kc + 2 < 8) {
                    const unsigned d = adst0 + (unsigned)(((kc + 2) % 3) * PA_CH) * 4;
                    const unsigned* s = hbase + (kc + 2) * PA_CH;
                    cpa16(d, s);
                    cpa16(d + 16, s + 4);
                    cpa_commit();
                }

                const unsigned* A  = a_s + (kc % 3) * PA_CH;
                const unsigned* Wc = wp + kc * 2048;
#pragma unroll
                for (int oi = 0; oi < 2; oi++) {
                    const int hex = ks * 2 + oi;
                    uint4 af[2];
#pragma unroll
                    for (int mi = 0; mi < 2; mi++)
                        af[mi] = *(const uint4*)(A + hex * 512 + (mt * 2 + mi) * 128 + lane * 4);
                    const unsigned* wb = Wc + hex * 256 + lane * 2;
#pragma unroll
                    for (int na = 0; na < 2; na++) {
                        const uint2 bv = *(const uint2*)(wb + (nt * 2 + na) * 64);
                        mma_f16(cfr[0][na], af[0].x, af[0].y, af[0].z, af[0].w, bv.x, bv.y);
                        mma_f16(cfr[1][na], af[1].x, af[1].y, af[1].z, af[1].w, bv.x, bv.y);
                    }
                }
            }
        }

        // Write K-split partials to this group's gs slice
        {
            float* slice = gs + ks * GS_SLICE;
#pragma unroll
            for (int mi = 0; mi < 2; mi++) {
                const int r0 = (mt * 32 + mi * 16 + g) * 33;
#pragma unroll
                for (int na = 0; na < 2; na++) {
                    const int c = nt * 16 + na * 8 + 2 * tig;
                    slice[r0 + c]              = cfr[mi][na][0];
                    slice[r0 + c + 1]          = cfr[mi][na][1];
                    slice[r0 + 8 * 33 + c]     = cfr[mi][na][2];
                    slice[r0 + 8 * 33 + c + 1] = cfr[mi][na][3];
                }
            }
        }
        __syncthreads();

        // Fused elementwise: sum 4 slices + x_gates, activations, cell update
        float s0 = 0.0f, s1 = 0.0f, s2 = 0.0f, s3 = 0.0f;
#pragma unroll
        for (int q = 0; q < 4; q++) {
            const float* gp = gs + q * GS_SLICE + cb_b * 33 + cu;
            s0 += gp[0];
            s1 += gp[8];
            s2 += gp[16];
            s3 += gp[24];
        }
        const float vi = s0 + xi;
        const float vf = s1 + xf;
        const float vg = s2 + xg2;
        const float vo = s3 + xo;

        c_st = sigf(vf) * c_st + sigf(vi) * tanh_f(vg);
        const float hn = sigf(vo) * tanh_f(c_st);

        outs[(size_t)t * NH + (size_t)cb_b * D_HIDDEN + j0 + cu] = hn;
        ((unsigned short*)g_h_perm[t & 1])[hw_word * 2 + hw_half] =
            __half_as_ushort(__float2half_rn(hn));

        if (t == T_STEPS - 1) {
            const size_t base = (size_t)T_STEPS * NH;
            if ((size_t)out_size >= base + 2 * (size_t)NH) {
                const size_t off = (size_t)cb_b * D_HIDDEN + j0 + cu;
                outs[base + off]      = hn;
                outs[base + NH + off] = c_st;
            }
        } else {
            // prefetch x_gates for t+1 (hides DRAM latency behind the barrier)
            const float* p = g_xgates + (size_t)(t + 1) * BATCH * G4
                           + (size_t)cb_b * G4 + j0 + cu;
            xi  = p[0];
            xf  = p[D_HIDDEN];
            xg2 = p[2 * D_HIDDEN];
            xo  = p[3 * D_HIDDEN];
            grid_barrier(t + 1);
        }
    }
}

// ---------------------------------------------------------------------------
extern "C" void kernel_launch(void* const* d_in, const int* in_sizes, int n_in,
                              void* d_out, int out_size)
{
    const int*   x_seq = (const int*)  d_in[0];
    const float* emb   = (const float*)d_in[1];
    const float* W_ih  = (const float*)d_in[2];
    const float* W_hh  = (const float*)d_in[3];
    const float* b_ih  = (const float*)d_in[4];
    const float* b_hh  = (const float*)d_in[5];
    float* out = (float*)d_out;

    cudaFuncSetAttribute(embed_gemm_f16,
                         cudaFuncAttributeMaxDynamicSharedMemorySize, E_SMEM_BYTES);
    cudaFuncSetAttribute(lstm_persistent,
                         cudaFuncAttributeMaxDynamicSharedMemorySize, P_SMEM_BYTES);

    init_kernel<<<1, 1>>>();

    // Pre-convert embedding + W_ih to packed fp16 (W_hh converts inside persistent)
    {
        unsigned* demb; cudaGetSymbolAddress((void**)&demb, g_emb_f16);
        unsigned* dwih; cudaGetSymbolAddress((void**)&dwih, g_wih_f16);
        int n4e = (VOCAB * D_EMBED) / 4;
        int n4i = (G4 * D_EMBED) / 4;
        cvt_f16_kernel<<<(n4e + 255) / 256, 256>>>((const float4*)emb,  (uint2*)demb, n4e);
        cvt_f16_kernel<<<(n4i + 255) / 256, 256>>>((const float4*)W_ih, (uint2*)dwih, n4i);
    }

    dim3 eg(G4 / 128, (T_STEPS * BATCH) / 128);   // (32, 128)
    embed_gemm_f16<<<eg, 256, E_SMEM_BYTES>>>(x_seq, b_ih, b_hh);

    lstm_persistent<<<NCTA, PTHREADS, P_SMEM_BYTES>>>(W_hh, out, out_size);
}